// round 1
// baseline (speedup 1.0000x reference)
#include <cuda_runtime.h>
#include <cuda_bf16.h>
#include <math.h>

// Problem constants
#define AA 16
#define BB 16
#define SS 128
#define DD 512
#define NN 256        // A*B
#define LL 5
#define SC 132        // S + L - 1
#define HH 8
#define DK 64

// ---------------- scratch (device globals; no runtime allocation) ----------------
__device__ float g_xcq[(size_t)NN*SC*DD];
__device__ float g_xck[(size_t)NN*SC*DD];
__device__ float g_yq [(size_t)NN*SC*DD];
__device__ float g_yk [(size_t)NN*SC*DD];
__device__ float g_wq [(size_t)NN*SS*LL];
__device__ float g_wk [(size_t)NN*SS*LL];
__device__ float g_q  [(size_t)NN*SS*DD];
__device__ float g_k  [(size_t)NN*SS*DD];
__device__ float g_v  [(size_t)NN*SS*DD];
__device__ float g_x1 [(size_t)NN*SS*DD];
__device__ float g_xa [(size_t)NN*SS*DD];
__device__ float g_xa2[(size_t)NN*SS*DD];
__device__ float g_xf [(size_t)NN*SS*DD];

// ---------------- concat pad (L-1 rows) + x along seq -> xc [N, 132, D] ----------
__global__ void k_concat(const float* __restrict__ x, const float* __restrict__ pad,
                         float* __restrict__ xc) {
    int idx = blockIdx.x * 256 + threadIdx.x;     // float4 index; total N*SC*128
    int c   = idx & 127;
    int row = idx >> 7;
    int n = row / SC;
    int s = row - n * SC;
    const float4* src;
    if (s < LL - 1)
        src = (const float4*)pad + ((size_t)n*(LL-1) + s)*128 + c;
    else
        src = (const float4*)x   + ((size_t)n*SS + (s - (LL-1)))*128 + c;
    ((float4*)xc)[idx] = *src;
}

// ---------------- sgemm: C[M,N] = A[M,K] * B[N,K]^T + bias[N] ---------------------
// 128x128 tile, BK=8, 256 threads, 8x8 per thread. M,N multiples of 128, K mult of 8.
__global__ void sgemm_nt(const float* __restrict__ Amat, const float* __restrict__ Bmat,
                         const float* __restrict__ bias, float* __restrict__ C,
                         int M, int Nn, int K) {
    __shared__ float As[8][128];
    __shared__ float Bs[8][128];
    int tid = threadIdx.x;
    int bm = blockIdx.y * 128;
    int bn = blockIdx.x * 128;
    int tx = tid & 15;
    int ty = tid >> 4;

    float acc[8][8];
#pragma unroll
    for (int i = 0; i < 8; i++)
#pragma unroll
        for (int j = 0; j < 8; j++) acc[i][j] = 0.f;

    int lr = tid >> 1;            // 0..127
    int lc = (tid & 1) * 4;       // 0 or 4
    const float* Aptr = Amat + (size_t)(bm + lr) * K + lc;
    const float* Bptr = Bmat + (size_t)(bn + lr) * K + lc;

    for (int kt = 0; kt < K; kt += 8) {
        float4 av = *(const float4*)(Aptr + kt);
        float4 bv = *(const float4*)(Bptr + kt);
        As[lc+0][lr] = av.x; As[lc+1][lr] = av.y; As[lc+2][lr] = av.z; As[lc+3][lr] = av.w;
        Bs[lc+0][lr] = bv.x; Bs[lc+1][lr] = bv.y; Bs[lc+2][lr] = bv.z; Bs[lc+3][lr] = bv.w;
        __syncthreads();
#pragma unroll
        for (int kk = 0; kk < 8; kk++) {
            float4 a0 = *(const float4*)&As[kk][ty*8];
            float4 a1 = *(const float4*)&As[kk][ty*8+4];
            float4 b0 = *(const float4*)&Bs[kk][tx*8];
            float4 b1 = *(const float4*)&Bs[kk][tx*8+4];
            float a[8] = {a0.x,a0.y,a0.z,a0.w,a1.x,a1.y,a1.z,a1.w};
            float b[8] = {b0.x,b0.y,b0.z,b0.w,b1.x,b1.y,b1.z,b1.w};
#pragma unroll
            for (int i = 0; i < 8; i++)
#pragma unroll
                for (int j = 0; j < 8; j++) acc[i][j] += a[i]*b[j];
        }
        __syncthreads();
    }

#pragma unroll
    for (int i = 0; i < 8; i++) {
        int row = bm + ty*8 + i;
        float* crow = C + (size_t)row * Nn + bn + tx*8;
#pragma unroll
        for (int j = 0; j < 8; j++) crow[j] = acc[i][j] + bias[bn + tx*8 + j];
    }
}

// ---------------- local-window softmax weights: w[n,s,5] --------------------------
__global__ void k_weights(const float* __restrict__ y, float* __restrict__ w) {
    int gw = blockIdx.x * 4 + (threadIdx.x >> 5);   // warp -> (n,s)
    int lane = threadIdx.x & 31;
    int n = gw >> 7;
    int s = gw & 127;
    const float* base = y + (size_t)n * SC * DD;
    const float* cen  = base + (size_t)(s + LL - 1) * DD;
    float d0=0.f,d1=0.f,d2=0.f,d3=0.f,d4=0.f;
    for (int i = lane; i < DD; i += 32) {
        float cv = cen[i];
        d0 += cv * base[(s+0)*DD + i];
        d1 += cv * base[(s+1)*DD + i];
        d2 += cv * base[(s+2)*DD + i];
        d3 += cv * base[(s+3)*DD + i];
        d4 += cv * base[(s+4)*DD + i];
    }
#pragma unroll
    for (int off = 16; off; off >>= 1) {
        d0 += __shfl_xor_sync(0xffffffffu, d0, off);
        d1 += __shfl_xor_sync(0xffffffffu, d1, off);
        d2 += __shfl_xor_sync(0xffffffffu, d2, off);
        d3 += __shfl_xor_sync(0xffffffffu, d3, off);
        d4 += __shfl_xor_sync(0xffffffffu, d4, off);
    }
    if (lane == 0) {
        const float sc = 0.044194173824159216f;  // 1/sqrt(512)
        float s0 = d0*sc, s1 = d1*sc, s2 = d2*sc, s3 = d3*sc, s4 = d4*sc;
        float m = fmaxf(fmaxf(fmaxf(s0,s1), fmaxf(s2,s3)), s4);
        float e0 = __expf(s0-m), e1 = __expf(s1-m), e2 = __expf(s2-m),
              e3 = __expf(s3-m), e4 = __expf(s4-m);
        float inv = 1.f / (e0+e1+e2+e3+e4);
        float* wp = w + (size_t)gw * LL;
        wp[0]=e0*inv; wp[1]=e1*inv; wp[2]=e2*inv; wp[3]=e3*inv; wp[4]=e4*inv;
    }
}

// ---------------- scrambled-reshape gather:
// out[n,s,d] = sum_l w[n, sp, lp] * y[n, sp+lp, d] with f=l*S+s, sp=f/5, lp=f%5 ----
__global__ void k_gather(const float* __restrict__ y, const float* __restrict__ w,
                         float* __restrict__ out) {
    int ns = blockIdx.x;           // n*128 + s
    int n = ns >> 7;
    int s = ns & 127;
    float coef[LL];
    int   rowi[LL];
#pragma unroll
    for (int l = 0; l < LL; l++) {
        int f  = l * SS + s;
        int sp = f / 5;
        int lp = f - sp * 5;
        coef[l] = w[((size_t)n * SS + sp) * LL + lp];
        rowi[l] = sp + lp;
    }
    const float4* yb = (const float4*)y + (size_t)n * SC * 128;
    int c = threadIdx.x;   // 0..127 float4 lanes
    float4 acc = make_float4(0.f,0.f,0.f,0.f);
#pragma unroll
    for (int l = 0; l < LL; l++) {
        float4 v = yb[(size_t)rowi[l] * 128 + c];
        acc.x += coef[l]*v.x; acc.y += coef[l]*v.y;
        acc.z += coef[l]*v.z; acc.w += coef[l]*v.w;
    }
    ((float4*)out)[(size_t)ns * 128 + c] = acc;
}

// ---------------- attention 1: per (n,h) block, S=128, dk=64 ----------------------
__global__ void k_attn1(const float* __restrict__ q, const float* __restrict__ k,
                        const float* __restrict__ v, float* __restrict__ o) {
    extern __shared__ float sm[];
    float* Ks = sm;                  // 128*64
    float* Vs = Ks + 128*64;         // 128*64
    float* Sc = Vs + 128*64;         // 128*129 (padded)
    int n = blockIdx.x / HH;
    int h = blockIdx.x % HH;
    int tid = threadIdx.x;           // 128 threads

    // load K,V head tiles into smem (float4)
    const float4* k4 = (const float4*)k;
    const float4* v4 = (const float4*)v;
    for (int it = tid; it < 128*16; it += 128) {
        int r = it >> 4, c = it & 15;
        size_t gidx = ((size_t)n*SS + r) * 128 + (size_t)h*16 + c;
        ((float4*)Ks)[it] = k4[gidx];
        ((float4*)Vs)[it] = v4[gidx];
    }
    __syncthreads();

    // q row in registers
    float4 qr[16];
    const float4* qrow = (const float4*)q + ((size_t)n*SS + tid) * 128 + (size_t)h*16;
#pragma unroll
    for (int c = 0; c < 16; c++) qr[c] = qrow[c];

    float* sc = Sc + (size_t)tid * 129;
    float mx = -1e30f;
    for (int j = 0; j < 128; j++) {
        const float4* kr = (const float4*)(Ks + j*64);
        float s = 0.f;
#pragma unroll
        for (int c = 0; c < 16; c++) {
            float4 kv = kr[c];
            s += qr[c].x*kv.x + qr[c].y*kv.y + qr[c].z*kv.z + qr[c].w*kv.w;
        }
        s *= 0.125f;                  // 1/sqrt(64)
        sc[j] = s;
        mx = fmaxf(mx, s);
    }
    float sum = 0.f;
    for (int j = 0; j < 128; j++) {
        float e = __expf(sc[j] - mx);
        sc[j] = e;
        sum += e;
    }
    float inv = 1.f / sum;

    float4* orow = (float4*)o + ((size_t)n*SS + tid) * 128 + (size_t)h*16;
#pragma unroll
    for (int c = 0; c < 16; c++) {
        float4 acc = make_float4(0.f,0.f,0.f,0.f);
        const float4* vcol = (const float4*)Vs + c;
        for (int j = 0; j < 128; j++) {
            float p = sc[j];
            float4 vv = vcol[j*16];
            acc.x += p*vv.x; acc.y += p*vv.y; acc.z += p*vv.z; acc.w += p*vv.w;
        }
        acc.x *= inv; acc.y *= inv; acc.z *= inv; acc.w *= inv;
        orow[c] = acc;
    }
}

// ---------------- transpose [A,B,S,D] -> [S,B,A,D] --------------------------------
__global__ void k_to_xa(const float* __restrict__ x1, float* __restrict__ xa) {
    int idx = blockIdx.x * 256 + threadIdx.x;   // float4 index over N*S*128
    int c = idx & 127;
    int row = idx >> 7;                         // (s*16+b)*16 + a
    int a  = row & 15;
    int sb = row >> 4;
    int b  = sb & 15;
    int s  = sb >> 4;
    size_t src = ((size_t)(a*BB + b) * SS + s) * 128 + c;
    ((float4*)xa)[idx] = ((const float4*)x1)[src];
}

// ---------------- transpose [S,B,A,D] -> [A,B,S,D] --------------------------------
__global__ void k_from_xa(const float* __restrict__ xa2, float* __restrict__ xf) {
    int idx = blockIdx.x * 256 + threadIdx.x;   // float4 index over N*S*128
    int c = idx & 127;
    int row = idx >> 7;                         // (a*16+b)*128 + s
    int s  = row & 127;
    int ab = row >> 7;
    int b  = ab & 15;
    int a  = ab >> 4;
    size_t src = ((size_t)(s*BB + b) * AA + a) * 128 + c;
    ((float4*)xf)[idx] = ((const float4*)xa2)[src];
}

// ---------------- attention 2: per sb row (2048), seq=A=16, 8 heads ---------------
__global__ void k_attn2(const float* __restrict__ xa, float* __restrict__ o) {
    __shared__ float hs[16*516];
    __shared__ float sc[16*16];
    __shared__ float ps[16*17];
    int sb = blockIdx.x;
    const float4* src = (const float4*)(xa + (size_t)sb * 16 * DD);
    for (int it = threadIdx.x; it < 16*128; it += 256) {
        int r = it >> 7, c = it & 127;
        float4 vv = src[it];
        float* dst = hs + r*516 + c*4;
        dst[0]=vv.x; dst[1]=vv.y; dst[2]=vv.z; dst[3]=vv.w;
    }
    __syncthreads();
    int i = threadIdx.x >> 4;
    int j = threadIdx.x & 15;
    for (int h = 0; h < HH; h++) {
        int base = h * 64;
        const float* hi = hs + i*516 + base;
        const float* hj = hs + j*516 + base;
        float dot = 0.f;
#pragma unroll
        for (int d = 0; d < 64; d++) dot += hi[d]*hj[d];
        sc[i*16 + j] = dot * 0.125f;
        __syncthreads();
        if (threadIdx.x < 16) {
            int r = threadIdx.x;
            float m = -1e30f;
            for (int jj = 0; jj < 16; jj++) m = fmaxf(m, sc[r*16+jj]);
            float sum = 0.f;
            for (int jj = 0; jj < 16; jj++) {
                float e = __expf(sc[r*16+jj] - m);
                ps[r*17+jj] = e;
                sum += e;
            }
            float inv = 1.f / sum;
            for (int jj = 0; jj < 16; jj++) ps[r*17+jj] *= inv;
        }
        __syncthreads();
        for (int e = threadIdx.x; e < 16*64; e += 256) {
            int r = e >> 6, d = e & 63;
            float acc = 0.f;
#pragma unroll
            for (int jj = 0; jj < 16; jj++) acc += ps[r*17+jj] * hs[jj*516 + base + d];
            o[((size_t)sb*16 + r) * DD + base + d] = acc;
        }
        __syncthreads();
    }
}

// =================================================================================
extern "C" void kernel_launch(void* const* d_in, const int* in_sizes, int n_in,
                              void* d_out, int out_size) {
    const float* query = (const float*)d_in[0];
    const float* key   = (const float*)d_in[1];
    const float* value = (const float*)d_in[2];
    // d_in[3] = mask (unused by reference)
    const float* padq  = (const float*)d_in[4];
    const float* padk  = (const float*)d_in[5];
    const float* Wq    = (const float*)d_in[6];
    const float* bq    = (const float*)d_in[7];
    const float* Wk    = (const float*)d_in[8];
    const float* bk    = (const float*)d_in[9];
    const float* Wv    = (const float*)d_in[10];
    const float* bv    = (const float*)d_in[11];
    const float* Wo    = (const float*)d_in[12];
    const float* bo    = (const float*)d_in[13];
    float* out = (float*)d_out;

    float *xcq, *xck, *yq, *yk, *wq, *wk, *q, *k, *v, *x1, *xa, *xa2, *xf;
    cudaGetSymbolAddress((void**)&xcq, g_xcq);
    cudaGetSymbolAddress((void**)&xck, g_xck);
    cudaGetSymbolAddress((void**)&yq,  g_yq);
    cudaGetSymbolAddress((void**)&yk,  g_yk);
    cudaGetSymbolAddress((void**)&wq,  g_wq);
    cudaGetSymbolAddress((void**)&wk,  g_wk);
    cudaGetSymbolAddress((void**)&q,   g_q);
    cudaGetSymbolAddress((void**)&k,   g_k);
    cudaGetSymbolAddress((void**)&v,   g_v);
    cudaGetSymbolAddress((void**)&x1,  g_x1);
    cudaGetSymbolAddress((void**)&xa,  g_xa);
    cudaGetSymbolAddress((void**)&xa2, g_xa2);
    cudaGetSymbolAddress((void**)&xf,  g_xf);

    const int conc_blocks = (NN*SC*128) / 256;   // 16896
    k_concat<<<conc_blocks, 256>>>(query, padq, xcq);
    k_concat<<<conc_blocks, 256>>>(key,   padk, xck);

    dim3 gproj(DD/128, (NN*SC)/128);             // (4, 264)
    sgemm_nt<<<gproj, 256>>>(xcq, Wq, bq, yq, NN*SC, DD, DD);
    sgemm_nt<<<gproj, 256>>>(xck, Wk, bk, yk, NN*SC, DD, DD);

    dim3 gv(DD/128, (NN*SS)/128);                // (4, 256)
    sgemm_nt<<<gv, 256>>>(value, Wv, bv, v, NN*SS, DD, DD);

    k_weights<<<(NN*SS)/4, 128>>>(yq, wq);
    k_weights<<<(NN*SS)/4, 128>>>(yk, wk);
    k_gather<<<NN*SS, 128>>>(yq, wq, q);
    k_gather<<<NN*SS, 128>>>(yk, wk, k);

    const int attn1_smem = (128*64*2 + 128*129) * 4;   // 131584 B
    cudaFuncSetAttribute(k_attn1, cudaFuncAttributeMaxDynamicSharedMemorySize, attn1_smem);
    k_attn1<<<NN*HH, 128, attn1_smem>>>(q, k, v, x1);

    const int tr_blocks = (NN*SS*128) / 256;     // 16384
    k_to_xa<<<tr_blocks, 256>>>(x1, xa);
    k_attn2<<<SS*BB, 256>>>(xa, xa2);
    k_from_xa<<<tr_blocks, 256>>>(xa2, xf);

    sgemm_nt<<<gv, 256>>>(xf, Wo, bo, out, NN*SS, DD, DD);
}

// round 3
// speedup vs baseline: 3.3844x; 3.3844x over previous
#include <cuda_runtime.h>
#include <cuda_bf16.h>
#include <math.h>

// Problem constants
#define AA 16
#define BB 16
#define SS 128
#define DD 512
#define NN 256        // A*B
#define LL 5
#define SC 132        // S + L - 1
#define HH 8
#define DK 64

// ---------------- scratch (device globals; no runtime allocation) ----------------
__device__ float g_xcq[(size_t)NN*SC*DD];
__device__ float g_xck[(size_t)NN*SC*DD];
__device__ float g_yq [(size_t)NN*SC*DD];
__device__ float g_yk [(size_t)NN*SC*DD];
__device__ float g_wq [(size_t)NN*SS*LL];
__device__ float g_wk [(size_t)NN*SS*LL];
__device__ float g_q  [(size_t)NN*SS*DD];
__device__ float g_k  [(size_t)NN*SS*DD];
__device__ float g_v  [(size_t)NN*SS*DD];
__device__ float g_x1 [(size_t)NN*SS*DD];
__device__ float g_xa [(size_t)NN*SS*DD];
__device__ float g_xa2[(size_t)NN*SS*DD];
__device__ float g_xf [(size_t)NN*SS*DD];

// ---------------- tf32 helpers ---------------------------------------------------
__device__ __forceinline__ unsigned f2tf32(float f) {
    unsigned u;
    asm("cvt.rna.tf32.f32 %0, %1;" : "=r"(u) : "f"(f));
    return u;
}

__device__ __forceinline__ void mma_tf32(float* d, const unsigned* a, const unsigned* b) {
    asm volatile(
        "mma.sync.aligned.m16n8k8.row.col.f32.tf32.tf32.f32 "
        "{%0,%1,%2,%3}, {%4,%5,%6,%7}, {%8,%9}, {%0,%1,%2,%3};"
        : "+f"(d[0]), "+f"(d[1]), "+f"(d[2]), "+f"(d[3])
        : "r"(a[0]), "r"(a[1]), "r"(a[2]), "r"(a[3]),
          "r"(b[0]), "r"(b[1]));
}

// ---------------- concat pad (L-1 rows) + x along seq -> xc [N, 132, D] ----------
__global__ void k_concat(const float* __restrict__ x, const float* __restrict__ pad,
                         float* __restrict__ xc) {
    int idx = blockIdx.x * 256 + threadIdx.x;     // float4 index; total N*SC*128
    int c   = idx & 127;
    int row = idx >> 7;
    int n = row / SC;
    int s = row - n * SC;
    const float4* src;
    if (s < LL - 1)
        src = (const float4*)pad + ((size_t)n*(LL-1) + s)*128 + c;
    else
        src = (const float4*)x   + ((size_t)n*SS + (s - (LL-1)))*128 + c;
    ((float4*)xc)[idx] = *src;
}

// ---------------- tf32 tensor-core GEMM: C[M,512] = A[M,512] @ W[512,512]^T + bias
// 128x128 block tile, BK=32, 256 threads (8 warps: 4m x 2n), warp tile 32x64.
#define AS_STR 36
__global__ void __launch_bounds__(256) gemm_tc(const float* __restrict__ A,
                                               const float* __restrict__ W,
                                               const float* __restrict__ bias,
                                               float* __restrict__ C) {
    __shared__ unsigned As[128 * AS_STR];
    __shared__ unsigned Bs[128 * AS_STR];
    int tid = threadIdx.x;
    int bm = blockIdx.y * 128;
    int bn = blockIdx.x * 128;
    int wid = tid >> 5, lane = tid & 31;
    int g = lane >> 2, tig = lane & 3;
    int wm = wid & 3, wn = wid >> 2;
    int m0 = wm * 32, n0 = wn * 64;

    float acc[2][8][4];
#pragma unroll
    for (int mt = 0; mt < 2; mt++)
#pragma unroll
        for (int nt = 0; nt < 8; nt++)
#pragma unroll
            for (int i = 0; i < 4; i++) acc[mt][nt][i] = 0.f;

    const float* Ab = A + (size_t)bm * 512;
    const float* Wb = W + (size_t)bn * 512;

    for (int kt = 0; kt < 512; kt += 32) {
#pragma unroll
        for (int i = 0; i < 4; i++) {
            int idx = tid + 256 * i;       // 0..1023
            int r = idx >> 3, qd = idx & 7;
            float4 va = *(const float4*)(Ab + (size_t)r * 512 + kt + qd * 4);
            float4 vb = *(const float4*)(Wb + (size_t)r * 512 + kt + qd * 4);
            uint4 ua = make_uint4(f2tf32(va.x), f2tf32(va.y), f2tf32(va.z), f2tf32(va.w));
            uint4 ub = make_uint4(f2tf32(vb.x), f2tf32(vb.y), f2tf32(vb.z), f2tf32(vb.w));
            *(uint4*)&As[r * AS_STR + qd * 4] = ua;
            *(uint4*)&Bs[r * AS_STR + qd * 4] = ub;
        }
        __syncthreads();
#pragma unroll
        for (int kc = 0; kc < 4; kc++) {
            int kb = kc * 8;
            unsigned af[2][4], bf[8][2];
#pragma unroll
            for (int mt = 0; mt < 2; mt++) {
                int row = m0 + mt * 16 + g;
                af[mt][0] = As[row * AS_STR + kb + tig];
                af[mt][1] = As[(row + 8) * AS_STR + kb + tig];
                af[mt][2] = As[row * AS_STR + kb + tig + 4];
                af[mt][3] = As[(row + 8) * AS_STR + kb + tig + 4];
            }
#pragma unroll
            for (int nt = 0; nt < 8; nt++) {
                int col = n0 + nt * 8 + g;
                bf[nt][0] = Bs[col * AS_STR + kb + tig];
                bf[nt][1] = Bs[col * AS_STR + kb + tig + 4];
            }
#pragma unroll
            for (int mt = 0; mt < 2; mt++)
#pragma unroll
                for (int nt = 0; nt < 8; nt++)
                    mma_tf32(acc[mt][nt], af[mt], bf[nt]);
        }
        __syncthreads();
    }

#pragma unroll
    for (int mt = 0; mt < 2; mt++) {
        int row = bm + m0 + mt * 16 + g;
#pragma unroll
        for (int nt = 0; nt < 8; nt++) {
            int col = bn + n0 + nt * 8 + 2 * tig;
            float b0 = bias[col], b1 = bias[col + 1];
            float2 lo = make_float2(acc[mt][nt][0] + b0, acc[mt][nt][1] + b1);
            float2 hi = make_float2(acc[mt][nt][2] + b0, acc[mt][nt][3] + b1);
            *(float2*)&C[(size_t)row * 512 + col] = lo;
            *(float2*)&C[(size_t)(row + 8) * 512 + col] = hi;
        }
    }
}

// ---------------- local-window softmax weights: w[n,s,5] --------------------------
__global__ void k_weights(const float* __restrict__ y, float* __restrict__ w) {
    int gw = blockIdx.x * 4 + (threadIdx.x >> 5);   // warp -> (n,s)
    int lane = threadIdx.x & 31;
    int n = gw >> 7;
    int s = gw & 127;
    const float* base = y + (size_t)n * SC * DD;
    const float* cen  = base + (size_t)(s + LL - 1) * DD;
    float d0=0.f,d1=0.f,d2=0.f,d3=0.f,d4=0.f;
    for (int i = lane; i < DD; i += 32) {
        float cv = cen[i];
        d0 += cv * base[(s+0)*DD + i];
        d1 += cv * base[(s+1)*DD + i];
        d2 += cv * base[(s+2)*DD + i];
        d3 += cv * base[(s+3)*DD + i];
        d4 += cv * base[(s+4)*DD + i];
    }
#pragma unroll
    for (int off = 16; off; off >>= 1) {
        d0 += __shfl_xor_sync(0xffffffffu, d0, off);
        d1 += __shfl_xor_sync(0xffffffffu, d1, off);
        d2 += __shfl_xor_sync(0xffffffffu, d2, off);
        d3 += __shfl_xor_sync(0xffffffffu, d3, off);
        d4 += __shfl_xor_sync(0xffffffffu, d4, off);
    }
    if (lane == 0) {
        const float sc = 0.044194173824159216f;  // 1/sqrt(512)
        float s0 = d0*sc, s1 = d1*sc, s2 = d2*sc, s3 = d3*sc, s4 = d4*sc;
        float m = fmaxf(fmaxf(fmaxf(s0,s1), fmaxf(s2,s3)), s4);
        float e0 = __expf(s0-m), e1 = __expf(s1-m), e2 = __expf(s2-m),
              e3 = __expf(s3-m), e4 = __expf(s4-m);
        float inv = 1.f / (e0+e1+e2+e3+e4);
        float* wp = w + (size_t)gw * LL;
        wp[0]=e0*inv; wp[1]=e1*inv; wp[2]=e2*inv; wp[3]=e3*inv; wp[4]=e4*inv;
    }
}

// ---------------- scrambled-reshape gather ---------------------------------------
__global__ void k_gather(const float* __restrict__ y, const float* __restrict__ w,
                         float* __restrict__ out) {
    int ns = blockIdx.x;           // n*128 + s
    int n = ns >> 7;
    int s = ns & 127;
    float coef[LL];
    int   rowi[LL];
#pragma unroll
    for (int l = 0; l < LL; l++) {
        int f  = l * SS + s;
        int sp = f / 5;
        int lp = f - sp * 5;
        coef[l] = w[((size_t)n * SS + sp) * LL + lp];
        rowi[l] = sp + lp;
    }
    const float4* yb = (const float4*)y + (size_t)n * SC * 128;
    int c = threadIdx.x;   // 0..127 float4 lanes
    float4 acc = make_float4(0.f,0.f,0.f,0.f);
#pragma unroll
    for (int l = 0; l < LL; l++) {
        float4 v = yb[(size_t)rowi[l] * 128 + c];
        acc.x += coef[l]*v.x; acc.y += coef[l]*v.y;
        acc.z += coef[l]*v.z; acc.w += coef[l]*v.w;
    }
    ((float4*)out)[(size_t)ns * 128 + c] = acc;
}

// ---------------- attention 1 via tf32 MMA: per (n,h) block, S=128, dk=64 --------
// smem word layout: Qs[128][68] @0, Ks[128][68] @8704, Ps[128][132] overlays @0,
// Vs[128][72] @17408, inv_l[128] @26624. Total 26752 words = 107008 B.
#define Q_STR 68
#define V_STR 72
#define P_STR 132
__global__ void __launch_bounds__(256) attn1_tc(const float* __restrict__ q,
                                                const float* __restrict__ k,
                                                const float* __restrict__ v,
                                                float* __restrict__ o) {
    extern __shared__ unsigned sm[];
    unsigned* Qs = sm;
    unsigned* Ks = sm + 128 * Q_STR;
    unsigned* Ps = sm;                       // overlay (valid after QK phase)
    unsigned* Vs = sm + 2 * 128 * Q_STR;
    float* inv_l = (float*)(Vs + 128 * V_STR);

    int n = blockIdx.x >> 3, h = blockIdx.x & 7;
    int tid = threadIdx.x;
    int lane = tid & 31;
    int g = lane >> 2, tig = lane & 3;
    int m0 = (tid >> 5) * 16;                // warp -> 16 rows

    // load Q,K,V head tiles, convert to tf32
#pragma unroll
    for (int i = 0; i < 8; i++) {
        int idx = tid + 256 * i;             // 0..2047
        int s = idx >> 4, dq = idx & 15;
        size_t goff = ((size_t)(n * 128 + s)) * 512 + h * 64 + dq * 4;
        float4 vq = *(const float4*)(q + goff);
        float4 vk = *(const float4*)(k + goff);
        float4 vv = *(const float4*)(v + goff);
        *(uint4*)&Qs[s * Q_STR + dq * 4] =
            make_uint4(f2tf32(vq.x), f2tf32(vq.y), f2tf32(vq.z), f2tf32(vq.w));
        *(uint4*)&Ks[s * Q_STR + dq * 4] =
            make_uint4(f2tf32(vk.x), f2tf32(vk.y), f2tf32(vk.z), f2tf32(vk.w));
        *(uint4*)&Vs[s * V_STR + dq * 4] =
            make_uint4(f2tf32(vv.x), f2tf32(vv.y), f2tf32(vv.z), f2tf32(vv.w));
    }
    __syncthreads();

    // scores = Q @ K^T  (warp: 16 rows x 128 cols)
    float acc[16][4];
#pragma unroll
    for (int nt = 0; nt < 16; nt++)
#pragma unroll
        for (int i = 0; i < 4; i++) acc[nt][i] = 0.f;

#pragma unroll
    for (int kc = 0; kc < 8; kc++) {
        int kb = kc * 8;
        unsigned af[4];
        af[0] = Qs[(m0 + g) * Q_STR + kb + tig];
        af[1] = Qs[(m0 + 8 + g) * Q_STR + kb + tig];
        af[2] = Qs[(m0 + g) * Q_STR + kb + tig + 4];
        af[3] = Qs[(m0 + 8 + g) * Q_STR + kb + tig + 4];
#pragma unroll
        for (int nt = 0; nt < 16; nt++) {
            unsigned bf[2];
            bf[0] = Ks[(nt * 8 + g) * Q_STR + kb + tig];
            bf[1] = Ks[(nt * 8 + g) * Q_STR + kb + tig + 4];
            mma_tf32(acc[nt], af, bf);
        }
    }
    __syncthreads();   // Q,K dead everywhere -> safe to overlay Ps

    float* Pf = (float*)Ps;
#pragma unroll
    for (int nt = 0; nt < 16; nt++) {
        int col = nt * 8 + 2 * tig;
        Pf[(m0 + g) * P_STR + col]     = acc[nt][0];
        Pf[(m0 + g) * P_STR + col + 1] = acc[nt][1];
        Pf[(m0 + 8 + g) * P_STR + col]     = acc[nt][2];
        Pf[(m0 + 8 + g) * P_STR + col + 1] = acc[nt][3];
    }
    __syncthreads();

    // softmax: 2 threads per row, exp stored tf32-rounded (unnormalized)
    {
        int r = tid >> 1;
        int halfc = (tid & 1) * 64;
        float* row = Pf + r * P_STR + halfc;
        float mx = -1e30f;
#pragma unroll
        for (int j = 0; j < 64; j++) mx = fmaxf(mx, row[j]);
        mx = fmaxf(mx, __shfl_xor_sync(0xffffffffu, mx, 1));
        float mxs = mx * 0.125f;
        float sum = 0.f;
#pragma unroll
        for (int j = 0; j < 64; j++) {
            float e = __expf(row[j] * 0.125f - mxs);
            sum += e;
            ((unsigned*)row)[j] = f2tf32(e);
        }
        sum += __shfl_xor_sync(0xffffffffu, sum, 1);
        if ((tid & 1) == 0) inv_l[r] = 1.f / sum;
    }
    __syncthreads();

    // out = P @ V  (warp: 16 rows x 64 cols)
    float oacc[8][4];
#pragma unroll
    for (int nt = 0; nt < 8; nt++)
#pragma unroll
        for (int i = 0; i < 4; i++) oacc[nt][i] = 0.f;

#pragma unroll
    for (int kc = 0; kc < 16; kc++) {
        int kb = kc * 8;
        unsigned af[4];
        af[0] = Ps[(m0 + g) * P_STR + kb + tig];
        af[1] = Ps[(m0 + 8 + g) * P_STR + kb + tig];
        af[2] = Ps[(m0 + g) * P_STR + kb + tig + 4];
        af[3] = Ps[(m0 + 8 + g) * P_STR + kb + tig + 4];
#pragma unroll
        for (int nt = 0; nt < 8; nt++) {
            unsigned bf[2];
            bf[0] = Vs[(kb + tig) * V_STR + nt * 8 + g];
            bf[1] = Vs[(kb + tig + 4) * V_STR + nt * 8 + g];
            mma_tf32(oacc[nt], af, bf);
        }
    }

    float il0 = inv_l[m0 + g];
    float il1 = inv_l[m0 + 8 + g];
    size_t rbase = ((size_t)(n * 128 + m0 + g)) * 512 + h * 64;
#pragma unroll
    for (int nt = 0; nt < 8; nt++) {
        int col = nt * 8 + 2 * tig;
        *(float2*)&o[rbase + col] =
            make_float2(oacc[nt][0] * il0, oacc[nt][1] * il0);
        *(float2*)&o[rbase + 8 * 512 + col] =
            make_float2(oacc[nt][2] * il1, oacc[nt][3] * il1);
    }
}

// ---------------- transpose [A,B,S,D] -> [S,B,A,D] --------------------------------
__global__ void k_to_xa(const float* __restrict__ x1, float* __restrict__ xa) {
    int idx = blockIdx.x * 256 + threadIdx.x;   // float4 index over N*S*128
    int c = idx & 127;
    int row = idx >> 7;                         // (s*16+b)*16 + a
    int a  = row & 15;
    int sb = row >> 4;
    int b  = sb & 15;
    int s  = sb >> 4;
    size_t src = ((size_t)(a*BB + b) * SS + s) * 128 + c;
    ((float4*)xa)[idx] = ((const float4*)x1)[src];
}

// ---------------- transpose [S,B,A,D] -> [A,B,S,D] --------------------------------
__global__ void k_from_xa(const float* __restrict__ xa2, float* __restrict__ xf) {
    int idx = blockIdx.x * 256 + threadIdx.x;   // float4 index over N*S*128
    int c = idx & 127;
    int row = idx >> 7;                         // (a*16+b)*128 + s
    int s  = row & 127;
    int ab = row >> 7;
    int b  = ab & 15;
    int a  = ab >> 4;
    size_t src = ((size_t)(s*BB + b) * AA + a) * 128 + c;
    ((float4*)xf)[idx] = ((const float4*)xa2)[src];
}

// ---------------- attention 2: per sb row (2048), seq=A=16, 8 heads ---------------
__global__ void k_attn2(const float* __restrict__ xa, float* __restrict__ o) {
    __shared__ float hs[16*516];
    __shared__ float sc[16*16];
    __shared__ float ps[16*17];
    int sb = blockIdx.x;
    const float4* src = (const float4*)(xa + (size_t)sb * 16 * DD);
    for (int it = threadIdx.x; it < 16*128; it += 256) {
        int r = it >> 7, c = it & 127;
        float4 vv = src[it];
        float* dst = hs + r*516 + c*4;
        dst[0]=vv.x; dst[1]=vv.y; dst[2]=vv.z; dst[3]=vv.w;
    }
    __syncthreads();
    int i = threadIdx.x >> 4;
    int j = threadIdx.x & 15;
    for (int h = 0; h < HH; h++) {
        int base = h * 64;
        const float* hi = hs + i*516 + base;
        const float* hj = hs + j*516 + base;
        float dot = 0.f;
#pragma unroll
        for (int d = 0; d < 64; d++) dot += hi[d]*hj[d];
        sc[i*16 + j] = dot * 0.125f;
        __syncthreads();
        if (threadIdx.x < 16) {
            int r = threadIdx.x;
            float m = -1e30f;
            for (int jj = 0; jj < 16; jj++) m = fmaxf(m, sc[r*16+jj]);
            float sum = 0.f;
            for (int jj = 0; jj < 16; jj++) {
                float e = __expf(sc[r*16+jj] - m);
                ps[r*17+jj] = e;
                sum += e;
            }
            float inv = 1.f / sum;
            for (int jj = 0; jj < 16; jj++) ps[r*17+jj] *= inv;
        }
        __syncthreads();
        for (int e = threadIdx.x; e < 16*64; e += 256) {
            int r = e >> 6, d = e & 63;
            float acc = 0.f;
#pragma unroll
            for (int jj = 0; jj < 16; jj++) acc += ps[r*17+jj] * hs[jj*516 + base + d];
            o[((size_t)sb*16 + r) * DD + base + d] = acc;
        }
        __syncthreads();
    }
}

// =================================================================================
extern "C" void kernel_launch(void* const* d_in, const int* in_sizes, int n_in,
                              void* d_out, int out_size) {
    const float* query = (const float*)d_in[0];
    const float* key   = (const float*)d_in[1];
    const float* value = (const float*)d_in[2];
    // d_in[3] = mask (unused by reference)
    const float* padq  = (const float*)d_in[4];
    const float* padk  = (const float*)d_in[5];
    const float* Wq    = (const float*)d_in[6];
    const float* bq    = (const float*)d_in[7];
    const float* Wk    = (const float*)d_in[8];
    const float* bk    = (const float*)d_in[9];
    const float* Wv    = (const float*)d_in[10];
    const float* bv    = (const float*)d_in[11];
    const float* Wo    = (const float*)d_in[12];
    const float* bo    = (const float*)d_in[13];
    float* out = (float*)d_out;

    float *xcq, *xck, *yq, *yk, *wq, *wk, *q, *k, *v, *x1, *xa, *xa2, *xf;
    cudaGetSymbolAddress((void**)&xcq, g_xcq);
    cudaGetSymbolAddress((void**)&xck, g_xck);
    cudaGetSymbolAddress((void**)&yq,  g_yq);
    cudaGetSymbolAddress((void**)&yk,  g_yk);
    cudaGetSymbolAddress((void**)&wq,  g_wq);
    cudaGetSymbolAddress((void**)&wk,  g_wk);
    cudaGetSymbolAddress((void**)&q,   g_q);
    cudaGetSymbolAddress((void**)&k,   g_k);
    cudaGetSymbolAddress((void**)&v,   g_v);
    cudaGetSymbolAddress((void**)&x1,  g_x1);
    cudaGetSymbolAddress((void**)&xa,  g_xa);
    cudaGetSymbolAddress((void**)&xa2, g_xa2);
    cudaGetSymbolAddress((void**)&xf,  g_xf);

    const int conc_blocks = (NN*SC*128) / 256;   // 16896
    k_concat<<<conc_blocks, 256>>>(query, padq, xcq);
    k_concat<<<conc_blocks, 256>>>(key,   padk, xck);

    dim3 gproj(DD/128, (NN*SC)/128);             // (4, 264)
    gemm_tc<<<gproj, 256>>>(xcq, Wq, bq, yq);
    gemm_tc<<<gproj, 256>>>(xck, Wk, bk, yk);

    dim3 gv(DD/128, (NN*SS)/128);                // (4, 256)
    gemm_tc<<<gv, 256>>>(value, Wv, bv, v);

    k_weights<<<(NN*SS)/4, 128>>>(yq, wq);
    k_weights<<<(NN*SS)/4, 128>>>(yk, wk);
    k_gather<<<NN*SS, 128>>>(yq, wq, q);
    k_gather<<<NN*SS, 128>>>(yk, wk, k);

    const int attn1_smem = 26752 * 4;            // 107008 B
    cudaFuncSetAttribute(attn1_tc, cudaFuncAttributeMaxDynamicSharedMemorySize, attn1_smem);
    attn1_tc<<<NN*HH, 256, attn1_smem>>>(q, k, v, x1);

    const int tr_blocks = (NN*SS*128) / 256;     // 16384
    k_to_xa<<<tr_blocks, 256>>>(x1, xa);
    k_attn2<<<SS*BB, 256>>>(xa, xa2);
    k_from_xa<<<tr_blocks, 256>>>(xa2, xf);

    gemm_tc<<<gv, 256>>>(xf, Wo, bo, out);
}

// round 4
// speedup vs baseline: 3.6877x; 1.0896x over previous
#include <cuda_runtime.h>
#include <cuda_bf16.h>
#include <math.h>

// Problem constants
#define AA 16
#define BB 16
#define SS 128
#define DD 512
#define NN 256        // A*B
#define LL 5
#define SC 132        // S + L - 1
#define HH 8
#define DK 64

// ---------------- scratch (device globals; no runtime allocation) ----------------
__device__ unsigned g_xcq[(size_t)NN*SC*DD];   // tf32
__device__ unsigned g_xck[(size_t)NN*SC*DD];   // tf32
__device__ float    g_yq [(size_t)NN*SC*DD];
__device__ float    g_yk [(size_t)NN*SC*DD];
__device__ float    g_wq [(size_t)NN*SS*LL];
__device__ float    g_wk [(size_t)NN*SS*LL];
__device__ float    g_q  [(size_t)NN*SS*DD];
__device__ float    g_k  [(size_t)NN*SS*DD];
__device__ float    g_v  [(size_t)NN*SS*DD];
__device__ unsigned g_vtf[(size_t)NN*SS*DD];   // tf32 value
__device__ float    g_xa [(size_t)NN*SS*DD];   // [S,B,A,D]
__device__ unsigned g_xf [(size_t)NN*SS*DD];   // tf32 [A,B,S,D]
__device__ unsigned g_Wt [4*(size_t)DD*DD];    // tf32 Wq,Wk,Wv,Wo

// ---------------- tf32 helpers ---------------------------------------------------
__device__ __forceinline__ unsigned f2tf32(float f) {
    unsigned u;
    asm("cvt.rna.tf32.f32 %0, %1;" : "=r"(u) : "f"(f));
    return u;
}

__device__ __forceinline__ void mma_tf32(float* d, const unsigned* a, const unsigned* b) {
    asm volatile(
        "mma.sync.aligned.m16n8k8.row.col.f32.tf32.tf32.f32 "
        "{%0,%1,%2,%3}, {%4,%5,%6,%7}, {%8,%9}, {%0,%1,%2,%3};"
        : "+f"(d[0]), "+f"(d[1]), "+f"(d[2]), "+f"(d[3])
        : "r"(a[0]), "r"(a[1]), "r"(a[2]), "r"(a[3]),
          "r"(b[0]), "r"(b[1]));
}

__device__ __forceinline__ void cp16(unsigned* smem_dst, const unsigned* gmem_src) {
    unsigned saddr = (unsigned)__cvta_generic_to_shared(smem_dst);
    asm volatile("cp.async.cg.shared.global [%0], [%1], 16;\n"
                 :: "r"(saddr), "l"(gmem_src));
}

// ---------------- elementwise f32 -> tf32 ----------------------------------------
__global__ void k_cvt(const float* __restrict__ src, unsigned* __restrict__ dst, int n4) {
    int i = blockIdx.x * 256 + threadIdx.x;
    if (i < n4) {
        float4 v = ((const float4*)src)[i];
        ((uint4*)dst)[i] = make_uint4(f2tf32(v.x), f2tf32(v.y), f2tf32(v.z), f2tf32(v.w));
    }
}

// ---------------- concat pad + x -> xc [N,132,D] in tf32 --------------------------
__global__ void k_concat_cvt(const float* __restrict__ x, const float* __restrict__ pad,
                             unsigned* __restrict__ xc) {
    int idx = blockIdx.x * 256 + threadIdx.x;     // float4 index; total N*SC*128
    int c   = idx & 127;
    int row = idx >> 7;
    int n = row / SC;
    int s = row - n * SC;
    const float4* src;
    if (s < LL - 1)
        src = (const float4*)pad + ((size_t)n*(LL-1) + s)*128 + c;
    else
        src = (const float4*)x   + ((size_t)n*SS + (s - (LL-1)))*128 + c;
    float4 v = *src;
    ((uint4*)xc)[idx] = make_uint4(f2tf32(v.x), f2tf32(v.y), f2tf32(v.z), f2tf32(v.w));
}

// ---------------- tf32 tensor-core GEMM, cp.async 2-stage double buffer ----------
// C[M,512] = A[M,512] @ W[512,512]^T + bias. A,W already tf32-in-u32.
// 128x128 block tile, BK=32, 256 threads (8 warps: 4m x 2n), warp tile 32x64.
#define AS_STR 36
#define STG_WORDS (128 * AS_STR)
__global__ void __launch_bounds__(256) gemm_tc2(const unsigned* __restrict__ A,
                                                const unsigned* __restrict__ W,
                                                const float* __restrict__ bias,
                                                float* __restrict__ C) {
    extern __shared__ unsigned sm[];   // [2 stages][As|Bs]
    int tid = threadIdx.x;
    int bm = blockIdx.y * 128;
    int bn = blockIdx.x * 128;
    int wid = tid >> 5, lane = tid & 31;
    int g = lane >> 2, tig = lane & 3;
    int wm = wid & 3, wn = wid >> 2;
    int m0 = wm * 32, n0 = wn * 64;

    const unsigned* Ab = A + (size_t)bm * 512;
    const unsigned* Wb = W + (size_t)bn * 512;

    float acc[2][8][4];
#pragma unroll
    for (int mt = 0; mt < 2; mt++)
#pragma unroll
        for (int nt = 0; nt < 8; nt++)
#pragma unroll
            for (int i = 0; i < 4; i++) acc[mt][nt][i] = 0.f;

    // prefetch lambda-ish: 4 float4 per matrix per thread
#define PREFETCH(kt, stg)                                                     \
    {                                                                         \
        unsigned* sA = sm + (stg) * 2 * STG_WORDS;                            \
        unsigned* sB = sA + STG_WORDS;                                        \
        _Pragma("unroll")                                                     \
        for (int i = 0; i < 4; i++) {                                         \
            int idx = tid + 256 * i;                                          \
            int r = idx >> 3, qd = idx & 7;                                   \
            cp16(sA + r * AS_STR + qd * 4, Ab + (size_t)r * 512 + (kt) + qd * 4); \
            cp16(sB + r * AS_STR + qd * 4, Wb + (size_t)r * 512 + (kt) + qd * 4); \
        }                                                                     \
        asm volatile("cp.async.commit_group;\n");                             \
    }

    PREFETCH(0, 0);

#pragma unroll 1
    for (int kt = 0; kt < 512; kt += 32) {
        int stg = (kt >> 5) & 1;
        if (kt + 32 < 512) {
            PREFETCH(kt + 32, stg ^ 1);
            asm volatile("cp.async.wait_group 1;\n");
        } else {
            asm volatile("cp.async.wait_group 0;\n");
        }
        __syncthreads();

        const unsigned* As = sm + stg * 2 * STG_WORDS;
        const unsigned* Bs = As + STG_WORDS;
#pragma unroll
        for (int kc = 0; kc < 4; kc++) {
            int kb = kc * 8;
            unsigned af[2][4], bf[8][2];
#pragma unroll
            for (int mt = 0; mt < 2; mt++) {
                int row = m0 + mt * 16 + g;
                af[mt][0] = As[row * AS_STR + kb + tig];
                af[mt][1] = As[(row + 8) * AS_STR + kb + tig];
                af[mt][2] = As[row * AS_STR + kb + tig + 4];
                af[mt][3] = As[(row + 8) * AS_STR + kb + tig + 4];
            }
#pragma unroll
            for (int nt = 0; nt < 8; nt++) {
                int col = n0 + nt * 8 + g;
                bf[nt][0] = Bs[col * AS_STR + kb + tig];
                bf[nt][1] = Bs[col * AS_STR + kb + tig + 4];
            }
#pragma unroll
            for (int mt = 0; mt < 2; mt++)
#pragma unroll
                for (int nt = 0; nt < 8; nt++)
                    mma_tf32(acc[mt][nt], af[mt], bf[nt]);
        }
        __syncthreads();
    }
#undef PREFETCH

#pragma unroll
    for (int mt = 0; mt < 2; mt++) {
        int row = bm + m0 + mt * 16 + g;
#pragma unroll
        for (int nt = 0; nt < 8; nt++) {
            int col = bn + n0 + nt * 8 + 2 * tig;
            float b0 = bias[col], b1 = bias[col + 1];
            float2 lo = make_float2(acc[mt][nt][0] + b0, acc[mt][nt][1] + b1);
            float2 hi = make_float2(acc[mt][nt][2] + b0, acc[mt][nt][3] + b1);
            *(float2*)&C[(size_t)row * 512 + col] = lo;
            *(float2*)&C[(size_t)(row + 8) * 512 + col] = hi;
        }
    }
}

// ---------------- local-window softmax weights: w[n,s,5] --------------------------
__global__ void k_weights(const float* __restrict__ y, float* __restrict__ w) {
    int gw = blockIdx.x * 4 + (threadIdx.x >> 5);   // warp -> (n,s)
    int lane = threadIdx.x & 31;
    int n = gw >> 7;
    int s = gw & 127;
    const float* base = y + (size_t)n * SC * DD;
    const float* cen  = base + (size_t)(s + LL - 1) * DD;
    float d0=0.f,d1=0.f,d2=0.f,d3=0.f,d4=0.f;
    for (int i = lane; i < DD; i += 32) {
        float cv = cen[i];
        d0 += cv * base[(s+0)*DD + i];
        d1 += cv * base[(s+1)*DD + i];
        d2 += cv * base[(s+2)*DD + i];
        d3 += cv * base[(s+3)*DD + i];
        d4 += cv * base[(s+4)*DD + i];
    }
#pragma unroll
    for (int off = 16; off; off >>= 1) {
        d0 += __shfl_xor_sync(0xffffffffu, d0, off);
        d1 += __shfl_xor_sync(0xffffffffu, d1, off);
        d2 += __shfl_xor_sync(0xffffffffu, d2, off);
        d3 += __shfl_xor_sync(0xffffffffu, d3, off);
        d4 += __shfl_xor_sync(0xffffffffu, d4, off);
    }
    if (lane == 0) {
        const float sc = 0.044194173824159216f;  // 1/sqrt(512)
        float s0 = d0*sc, s1 = d1*sc, s2 = d2*sc, s3 = d3*sc, s4 = d4*sc;
        float m = fmaxf(fmaxf(fmaxf(s0,s1), fmaxf(s2,s3)), s4);
        float e0 = __expf(s0-m), e1 = __expf(s1-m), e2 = __expf(s2-m),
              e3 = __expf(s3-m), e4 = __expf(s4-m);
        float inv = 1.f / (e0+e1+e2+e3+e4);
        float* wp = w + (size_t)gw * LL;
        wp[0]=e0*inv; wp[1]=e1*inv; wp[2]=e2*inv; wp[3]=e3*inv; wp[4]=e4*inv;
    }
}

// ---------------- scrambled-reshape gather ---------------------------------------
__global__ void k_gather(const float* __restrict__ y, const float* __restrict__ w,
                         float* __restrict__ out) {
    int ns = blockIdx.x;           // n*128 + s
    int n = ns >> 7;
    int s = ns & 127;
    float coef[LL];
    int   rowi[LL];
#pragma unroll
    for (int l = 0; l < LL; l++) {
        int f  = l * SS + s;
        int sp = f / 5;
        int lp = f - sp * 5;
        coef[l] = w[((size_t)n * SS + sp) * LL + lp];
        rowi[l] = sp + lp;
    }
    const float4* yb = (const float4*)y + (size_t)n * SC * 128;
    int c = threadIdx.x;   // 0..127 float4 lanes
    float4 acc = make_float4(0.f,0.f,0.f,0.f);
#pragma unroll
    for (int l = 0; l < LL; l++) {
        float4 v = yb[(size_t)rowi[l] * 128 + c];
        acc.x += coef[l]*v.x; acc.y += coef[l]*v.y;
        acc.z += coef[l]*v.z; acc.w += coef[l]*v.w;
    }
    ((float4*)out)[(size_t)ns * 128 + c] = acc;
}

// ---------------- attention 1 via tf32 MMA: per (n,h) block, S=128, dk=64 --------
// Writes output directly in [S,B,A,D] layout (fuses the x1->xa transpose).
#define Q_STR 68
#define V_STR 72
#define P_STR 132
__global__ void __launch_bounds__(256) attn1_tc(const float* __restrict__ q,
                                                const float* __restrict__ k,
                                                const float* __restrict__ v,
                                                float* __restrict__ o) {
    extern __shared__ unsigned sm[];
    unsigned* Qs = sm;
    unsigned* Ks = sm + 128 * Q_STR;
    unsigned* Ps = sm;                       // overlay (valid after QK phase)
    unsigned* Vs = sm + 2 * 128 * Q_STR;
    float* inv_l = (float*)(Vs + 128 * V_STR);

    int n = blockIdx.x >> 3, h = blockIdx.x & 7;
    int tid = threadIdx.x;
    int lane = tid & 31;
    int g = lane >> 2, tig = lane & 3;
    int m0 = (tid >> 5) * 16;                // warp -> 16 rows

    // load Q,K,V head tiles, convert to tf32
#pragma unroll
    for (int i = 0; i < 8; i++) {
        int idx = tid + 256 * i;             // 0..2047
        int s = idx >> 4, dq = idx & 15;
        size_t goff = ((size_t)(n * 128 + s)) * 512 + h * 64 + dq * 4;
        float4 vq = *(const float4*)(q + goff);
        float4 vk = *(const float4*)(k + goff);
        float4 vv = *(const float4*)(v + goff);
        *(uint4*)&Qs[s * Q_STR + dq * 4] =
            make_uint4(f2tf32(vq.x), f2tf32(vq.y), f2tf32(vq.z), f2tf32(vq.w));
        *(uint4*)&Ks[s * Q_STR + dq * 4] =
            make_uint4(f2tf32(vk.x), f2tf32(vk.y), f2tf32(vk.z), f2tf32(vk.w));
        *(uint4*)&Vs[s * V_STR + dq * 4] =
            make_uint4(f2tf32(vv.x), f2tf32(vv.y), f2tf32(vv.z), f2tf32(vv.w));
    }
    __syncthreads();

    // scores = Q @ K^T  (warp: 16 rows x 128 cols)
    float acc[16][4];
#pragma unroll
    for (int nt = 0; nt < 16; nt++)
#pragma unroll
        for (int i = 0; i < 4; i++) acc[nt][i] = 0.f;

#pragma unroll
    for (int kc = 0; kc < 8; kc++) {
        int kb = kc * 8;
        unsigned af[4];
        af[0] = Qs[(m0 + g) * Q_STR + kb + tig];
        af[1] = Qs[(m0 + 8 + g) * Q_STR + kb + tig];
        af[2] = Qs[(m0 + g) * Q_STR + kb + tig + 4];
        af[3] = Qs[(m0 + 8 + g) * Q_STR + kb + tig + 4];
#pragma unroll
        for (int nt = 0; nt < 16; nt++) {
            unsigned bf[2];
            bf[0] = Ks[(nt * 8 + g) * Q_STR + kb + tig];
            bf[1] = Ks[(nt * 8 + g) * Q_STR + kb + tig + 4];
            mma_tf32(acc[nt], af, bf);
        }
    }
    __syncthreads();   // Q,K dead everywhere -> safe to overlay Ps

    float* Pf = (float*)Ps;
#pragma unroll
    for (int nt = 0; nt < 16; nt++) {
        int col = nt * 8 + 2 * tig;
        Pf[(m0 + g) * P_STR + col]     = acc[nt][0];
        Pf[(m0 + g) * P_STR + col + 1] = acc[nt][1];
        Pf[(m0 + 8 + g) * P_STR + col]     = acc[nt][2];
        Pf[(m0 + 8 + g) * P_STR + col + 1] = acc[nt][3];
    }
    __syncthreads();

    // softmax: 2 threads per row, exp stored tf32-rounded (unnormalized)
    {
        int r = tid >> 1;
        int halfc = (tid & 1) * 64;
        float* row = Pf + r * P_STR + halfc;
        float mx = -1e30f;
#pragma unroll
        for (int j = 0; j < 64; j++) mx = fmaxf(mx, row[j]);
        mx = fmaxf(mx, __shfl_xor_sync(0xffffffffu, mx, 1));
        float mxs = mx * 0.125f;
        float sum = 0.f;
#pragma unroll
        for (int j = 0; j < 64; j++) {
            float e = __expf(row[j] * 0.125f - mxs);
            sum += e;
            ((unsigned*)row)[j] = f2tf32(e);
        }
        sum += __shfl_xor_sync(0xffffffffu, sum, 1);
        if ((tid & 1) == 0) inv_l[r] = 1.f / sum;
    }
    __syncthreads();

    // out = P @ V  (warp: 16 rows x 64 cols)
    float oacc[8][4];
#pragma unroll
    for (int nt = 0; nt < 8; nt++)
#pragma unroll
        for (int i = 0; i < 4; i++) oacc[nt][i] = 0.f;

#pragma unroll
    for (int kc = 0; kc < 16; kc++) {
        int kb = kc * 8;
        unsigned af[4];
        af[0] = Ps[(m0 + g) * P_STR + kb + tig];
        af[1] = Ps[(m0 + 8 + g) * P_STR + kb + tig];
        af[2] = Ps[(m0 + g) * P_STR + kb + tig + 4];
        af[3] = Ps[(m0 + 8 + g) * P_STR + kb + tig + 4];
#pragma unroll
        for (int nt = 0; nt < 8; nt++) {
            unsigned bf[2];
            bf[0] = Vs[(kb + tig) * V_STR + nt * 8 + g];
            bf[1] = Vs[(kb + tig + 4) * V_STR + nt * 8 + g];
            mma_tf32(oacc[nt], af, bf);
        }
    }

    float il0 = inv_l[m0 + g];
    float il1 = inv_l[m0 + 8 + g];
    // output in [S,B,A,D]: row(s) = s*256 + b*16 + a where n = a*16+b
    int a = n >> 4, b = n & 15;
    int s0 = m0 + g, s1 = m0 + 8 + g;
    size_t r0 = ((size_t)(s0 * 256 + b * 16 + a)) * 512 + h * 64;
    size_t r1 = ((size_t)(s1 * 256 + b * 16 + a)) * 512 + h * 64;
#pragma unroll
    for (int nt = 0; nt < 8; nt++) {
        int col = nt * 8 + 2 * tig;
        *(float2*)&o[r0 + col] =
            make_float2(oacc[nt][0] * il0, oacc[nt][1] * il0);
        *(float2*)&o[r1 + col] =
            make_float2(oacc[nt][2] * il1, oacc[nt][3] * il1);
    }
}

// ---------------- attention 2: per sb row (2048), seq=A=16, 8 heads ---------------
// Reads xa [S,B,A,D]; writes xf in [A,B,S,D] layout as tf32 (fuses transpose+cvt).
__global__ void k_attn2(const float* __restrict__ xa, unsigned* __restrict__ o) {
    __shared__ float hs[16*516];
    __shared__ float sc[16*16];
    __shared__ float ps[16*17];
    int sb = blockIdx.x;                      // s*16 + b
    int s_idx = sb >> 4, b_idx = sb & 15;
    const float4* src = (const float4*)(xa + (size_t)sb * 16 * DD);
    for (int it = threadIdx.x; it < 16*128; it += 256) {
        int r = it >> 7, c = it & 127;
        float4 vv = src[it];
        float* dst = hs + r*516 + c*4;
        dst[0]=vv.x; dst[1]=vv.y; dst[2]=vv.z; dst[3]=vv.w;
    }
    __syncthreads();
    int i = threadIdx.x >> 4;
    int j = threadIdx.x & 15;
    for (int h = 0; h < HH; h++) {
        int base = h * 64;
        const float* hi = hs + i*516 + base;
        const float* hj = hs + j*516 + base;
        float dot = 0.f;
#pragma unroll
        for (int d = 0; d < 64; d++) dot += hi[d]*hj[d];
        sc[i*16 + j] = dot * 0.125f;
        __syncthreads();
        if (threadIdx.x < 16) {
            int r = threadIdx.x;
            float m = -1e30f;
            for (int jj = 0; jj < 16; jj++) m = fmaxf(m, sc[r*16+jj]);
            float sum = 0.f;
            for (int jj = 0; jj < 16; jj++) {
                float e = __expf(sc[r*16+jj] - m);
                ps[r*17+jj] = e;
                sum += e;
            }
            float inv = 1.f / sum;
            for (int jj = 0; jj < 16; jj++) ps[r*17+jj] *= inv;
        }
        __syncthreads();
        for (int e = threadIdx.x; e < 16*64; e += 256) {
            int r = e >> 6, d = e & 63;     // r = a index
            float acc = 0.f;
#pragma unroll
            for (int jj = 0; jj < 16; jj++) acc += ps[r*17+jj] * hs[jj*516 + base + d];
            // dst row in [A,B,S,D]: (a*16+b)*128 + s
            o[((size_t)((r*16 + b_idx)*128 + s_idx)) * DD + base + d] = f2tf32(acc);
        }
        __syncthreads();
    }
}

// =================================================================================
extern "C" void kernel_launch(void* const* d_in, const int* in_sizes, int n_in,
                              void* d_out, int out_size) {
    const float* query = (const float*)d_in[0];
    const float* key   = (const float*)d_in[1];
    const float* value = (const float*)d_in[2];
    // d_in[3] = mask (unused by reference)
    const float* padq  = (const float*)d_in[4];
    const float* padk  = (const float*)d_in[5];
    const float* Wq    = (const float*)d_in[6];
    const float* bq    = (const float*)d_in[7];
    const float* Wk    = (const float*)d_in[8];
    const float* bk    = (const float*)d_in[9];
    const float* Wv    = (const float*)d_in[10];
    const float* bv    = (const float*)d_in[11];
    const float* Wo    = (const float*)d_in[12];
    const float* bo    = (const float*)d_in[13];
    float* out = (float*)d_out;

    unsigned *xcq, *xck, *vtf, *xf, *Wt;
    float *yq, *yk, *wq, *wk, *q, *k, *v, *xa;
    cudaGetSymbolAddress((void**)&xcq, g_xcq);
    cudaGetSymbolAddress((void**)&xck, g_xck);
    cudaGetSymbolAddress((void**)&yq,  g_yq);
    cudaGetSymbolAddress((void**)&yk,  g_yk);
    cudaGetSymbolAddress((void**)&wq,  g_wq);
    cudaGetSymbolAddress((void**)&wk,  g_wk);
    cudaGetSymbolAddress((void**)&q,   g_q);
    cudaGetSymbolAddress((void**)&k,   g_k);
    cudaGetSymbolAddress((void**)&v,   g_v);
    cudaGetSymbolAddress((void**)&vtf, g_vtf);
    cudaGetSymbolAddress((void**)&xa,  g_xa);
    cudaGetSymbolAddress((void**)&xf,  g_xf);
    cudaGetSymbolAddress((void**)&Wt,  g_Wt);

    const size_t WSZ = (size_t)DD * DD;

    // --- input conversions ---
    const int conc_blocks = (NN*SC*128) / 256;   // 16896
    k_concat_cvt<<<conc_blocks, 256>>>(query, padq, xcq);
    k_concat_cvt<<<conc_blocks, 256>>>(key,   padk, xck);
    k_cvt<<<(int)(WSZ/4 + 255)/256, 256>>>(Wq, Wt + 0*WSZ, (int)(WSZ/4));
    k_cvt<<<(int)(WSZ/4 + 255)/256, 256>>>(Wk, Wt + 1*WSZ, (int)(WSZ/4));
    k_cvt<<<(int)(WSZ/4 + 255)/256, 256>>>(Wv, Wt + 2*WSZ, (int)(WSZ/4));
    k_cvt<<<(int)(WSZ/4 + 255)/256, 256>>>(Wo, Wt + 3*WSZ, (int)(WSZ/4));
    k_cvt<<<(NN*SS*DD/4 + 255)/256, 256>>>(value, vtf, NN*SS*DD/4);

    // --- projections (tensor-core, cp.async pipelined) ---
    const int gemm_smem = 2 * 2 * STG_WORDS * 4;   // 73728 B
    cudaFuncSetAttribute(gemm_tc2, cudaFuncAttributeMaxDynamicSharedMemorySize, gemm_smem);
    dim3 gproj(DD/128, (NN*SC)/128);             // (4, 264)
    gemm_tc2<<<gproj, 256, gemm_smem>>>(xcq, Wt + 0*WSZ, bq, yq);
    gemm_tc2<<<gproj, 256, gemm_smem>>>(xck, Wt + 1*WSZ, bk, yk);
    dim3 gv(DD/128, (NN*SS)/128);                // (4, 256)
    gemm_tc2<<<gv, 256, gemm_smem>>>(vtf, Wt + 2*WSZ, bv, v);

    // --- local window reweighting ---
    k_weights<<<(NN*SS)/4, 128>>>(yq, wq);
    k_weights<<<(NN*SS)/4, 128>>>(yk, wk);
    k_gather<<<NN*SS, 128>>>(yq, wq, q);
    k_gather<<<NN*SS, 128>>>(yk, wk, k);

    // --- attention 1 (writes [S,B,A,D]) ---
    const int attn1_smem = 26752 * 4;            // 107008 B
    cudaFuncSetAttribute(attn1_tc, cudaFuncAttributeMaxDynamicSharedMemorySize, attn1_smem);
    attn1_tc<<<NN*HH, 256, attn1_smem>>>(q, k, v, xa);

    // --- attention 2 (reads [S,B,A,D], writes tf32 [A,B,S,D]) ---
    k_attn2<<<SS*BB, 256>>>(xa, xf);

    // --- output projection ---
    gemm_tc2<<<gv, 256, gemm_smem>>>(xf, Wt + 3*WSZ, bo, out);
}

// round 5
// speedup vs baseline: 3.7121x; 1.0066x over previous
#include <cuda_runtime.h>
#include <cuda_bf16.h>
#include <math.h>

// Problem constants
#define AA 16
#define BB 16
#define SS 128
#define DD 512
#define NN 256        // A*B
#define LL 5
#define SC 132        // S + L - 1
#define HH 8
#define DK 64

// ---------------- scratch (device globals; no runtime allocation) ----------------
__device__ unsigned g_xcq[(size_t)NN*SC*DD];   // tf32
__device__ unsigned g_xck[(size_t)NN*SC*DD];   // tf32
__device__ float    g_yq [(size_t)NN*SC*DD];
__device__ float    g_yk [(size_t)NN*SC*DD];
__device__ float    g_wq [(size_t)NN*SS*LL];
__device__ float    g_wk [(size_t)NN*SS*LL];
__device__ float    g_q  [(size_t)NN*SS*DD];
__device__ float    g_k  [(size_t)NN*SS*DD];
__device__ float    g_v  [(size_t)NN*SS*DD];
__device__ unsigned g_vtf[(size_t)NN*SS*DD];   // tf32 value
__device__ float    g_xa [(size_t)NN*SS*DD];   // [S,B,A,D]
__device__ unsigned g_xf [(size_t)NN*SS*DD];   // tf32 [A,B,S,D]
__device__ unsigned g_Wt [4*(size_t)DD*DD];    // tf32 Wq,Wk,Wv,Wo

// ---------------- tf32 helpers ---------------------------------------------------
__device__ __forceinline__ unsigned f2tf32(float f) {
    unsigned u;
    asm("cvt.rna.tf32.f32 %0, %1;" : "=r"(u) : "f"(f));
    return u;
}

__device__ __forceinline__ void mma_tf32(float* d, const unsigned* a, const unsigned* b) {
    asm volatile(
        "mma.sync.aligned.m16n8k8.row.col.f32.tf32.tf32.f32 "
        "{%0,%1,%2,%3}, {%4,%5,%6,%7}, {%8,%9}, {%0,%1,%2,%3};"
        : "+f"(d[0]), "+f"(d[1]), "+f"(d[2]), "+f"(d[3])
        : "r"(a[0]), "r"(a[1]), "r"(a[2]), "r"(a[3]),
          "r"(b[0]), "r"(b[1]));
}

__device__ __forceinline__ void cp16(unsigned* smem_dst, const unsigned* gmem_src) {
    unsigned saddr = (unsigned)__cvta_generic_to_shared(smem_dst);
    asm volatile("cp.async.cg.shared.global [%0], [%1], 16;\n"
                 :: "r"(saddr), "l"(gmem_src));
}

// ---------------- elementwise f32 -> tf32 ----------------------------------------
__global__ void k_cvt(const float* __restrict__ src, unsigned* __restrict__ dst, int n4) {
    int i = blockIdx.x * 256 + threadIdx.x;
    if (i < n4) {
        float4 v = ((const float4*)src)[i];
        ((uint4*)dst)[i] = make_uint4(f2tf32(v.x), f2tf32(v.y), f2tf32(v.z), f2tf32(v.w));
    }
}

// ---------------- concat pad + x -> xc [N,132,D] in tf32 --------------------------
__global__ void k_concat_cvt(const float* __restrict__ x, const float* __restrict__ pad,
                             unsigned* __restrict__ xc) {
    int idx = blockIdx.x * 256 + threadIdx.x;     // float4 index; total N*SC*128
    int c   = idx & 127;
    int row = idx >> 7;
    int n = row / SC;
    int s = row - n * SC;
    const float4* src;
    if (s < LL - 1)
        src = (const float4*)pad + ((size_t)n*(LL-1) + s)*128 + c;
    else
        src = (const float4*)x   + ((size_t)n*SS + (s - (LL-1)))*128 + c;
    float4 v = *src;
    ((uint4*)xc)[idx] = make_uint4(f2tf32(v.x), f2tf32(v.y), f2tf32(v.z), f2tf32(v.w));
}

// ---------------- tf32 tensor-core GEMM, cp.async 3-stage pipeline ---------------
// C[M,512] = A[M,512] @ W[512,512]^T + bias. A,W already tf32-in-u32.
// 128x128 block tile, BK=32, 256 threads (8 warps: 4m x 2n), warp tile 32x64.
#define AS_STR 36
#define STG_WORDS (128 * AS_STR)
#define NSTG 3
__global__ void __launch_bounds__(256) gemm_tc3(const unsigned* __restrict__ A,
                                                const unsigned* __restrict__ W,
                                                const float* __restrict__ bias,
                                                float* __restrict__ C) {
    extern __shared__ unsigned sm[];   // [NSTG stages][As|Bs]
    int tid = threadIdx.x;
    int bm = blockIdx.y * 128;
    int bn = blockIdx.x * 128;
    int wid = tid >> 5, lane = tid & 31;
    int g = lane >> 2, tig = lane & 3;
    int wm = wid & 3, wn = wid >> 2;
    int m0 = wm * 32, n0 = wn * 64;

    const unsigned* Ab = A + (size_t)bm * 512;
    const unsigned* Wb = W + (size_t)bn * 512;

    float acc[2][8][4];
#pragma unroll
    for (int mt = 0; mt < 2; mt++)
#pragma unroll
        for (int nt = 0; nt < 8; nt++)
#pragma unroll
            for (int i = 0; i < 4; i++) acc[mt][nt][i] = 0.f;

#define PREFETCH(kt, stg)                                                     \
    {                                                                         \
        unsigned* sA = sm + (stg) * 2 * STG_WORDS;                            \
        unsigned* sB = sA + STG_WORDS;                                        \
        _Pragma("unroll")                                                     \
        for (int i = 0; i < 4; i++) {                                         \
            int idx = tid + 256 * i;                                          \
            int r = idx >> 3, qd = idx & 7;                                   \
            cp16(sA + r * AS_STR + qd * 4, Ab + (size_t)r * 512 + (kt) + qd * 4); \
            cp16(sB + r * AS_STR + qd * 4, Wb + (size_t)r * 512 + (kt) + qd * 4); \
        }                                                                     \
        asm volatile("cp.async.commit_group;\n");                             \
    }

    PREFETCH(0, 0);
    PREFETCH(32, 1);

#pragma unroll 1
    for (int kt = 0; kt < 512; kt += 32) {
        int it = kt >> 5;
        int stg = it % NSTG;
        asm volatile("cp.async.wait_group 1;\n");
        __syncthreads();
        if (kt + 64 < 512) {
            PREFETCH(kt + 64, (stg + 2) % NSTG);
        } else {
            asm volatile("cp.async.commit_group;\n");   // keep group count in lockstep
        }

        const unsigned* As = sm + stg * 2 * STG_WORDS;
        const unsigned* Bs = As + STG_WORDS;
#pragma unroll
        for (int kc = 0; kc < 4; kc++) {
            int kb = kc * 8;
            unsigned af[2][4], bf[8][2];
#pragma unroll
            for (int mt = 0; mt < 2; mt++) {
                int row = m0 + mt * 16 + g;
                af[mt][0] = As[row * AS_STR + kb + tig];
                af[mt][1] = As[(row + 8) * AS_STR + kb + tig];
                af[mt][2] = As[row * AS_STR + kb + tig + 4];
                af[mt][3] = As[(row + 8) * AS_STR + kb + tig + 4];
            }
#pragma unroll
            for (int nt = 0; nt < 8; nt++) {
                int col = n0 + nt * 8 + g;
                bf[nt][0] = Bs[col * AS_STR + kb + tig];
                bf[nt][1] = Bs[col * AS_STR + kb + tig + 4];
            }
#pragma unroll
            for (int mt = 0; mt < 2; mt++)
#pragma unroll
                for (int nt = 0; nt < 8; nt++)
                    mma_tf32(acc[mt][nt], af[mt], bf[nt]);
        }
    }
#undef PREFETCH

#pragma unroll
    for (int mt = 0; mt < 2; mt++) {
        int row = bm + m0 + mt * 16 + g;
#pragma unroll
        for (int nt = 0; nt < 8; nt++) {
            int col = bn + n0 + nt * 8 + 2 * tig;
            float b0 = bias[col], b1 = bias[col + 1];
            float2 lo = make_float2(acc[mt][nt][0] + b0, acc[mt][nt][1] + b1);
            float2 hi = make_float2(acc[mt][nt][2] + b0, acc[mt][nt][3] + b1);
            *(float2*)&C[(size_t)row * 512 + col] = lo;
            *(float2*)&C[(size_t)(row + 8) * 512 + col] = hi;
        }
    }
}

// ---------------- local-window softmax weights: w[n,s,5] --------------------------
__global__ void k_weights(const float* __restrict__ y, float* __restrict__ w) {
    int gw = blockIdx.x * 4 + (threadIdx.x >> 5);   // warp -> (n,s)
    int lane = threadIdx.x & 31;
    int n = gw >> 7;
    int s = gw & 127;
    const float* base = y + (size_t)n * SC * DD;
    const float* cen  = base + (size_t)(s + LL - 1) * DD;
    float d0=0.f,d1=0.f,d2=0.f,d3=0.f,d4=0.f;
    for (int i = lane; i < DD; i += 32) {
        float cv = cen[i];
        d0 += cv * base[(s+0)*DD + i];
        d1 += cv * base[(s+1)*DD + i];
        d2 += cv * base[(s+2)*DD + i];
        d3 += cv * base[(s+3)*DD + i];
        d4 += cv * base[(s+4)*DD + i];
    }
#pragma unroll
    for (int off = 16; off; off >>= 1) {
        d0 += __shfl_xor_sync(0xffffffffu, d0, off);
        d1 += __shfl_xor_sync(0xffffffffu, d1, off);
        d2 += __shfl_xor_sync(0xffffffffu, d2, off);
        d3 += __shfl_xor_sync(0xffffffffu, d3, off);
        d4 += __shfl_xor_sync(0xffffffffu, d4, off);
    }
    if (lane == 0) {
        const float sc = 0.044194173824159216f;  // 1/sqrt(512)
        float s0 = d0*sc, s1 = d1*sc, s2 = d2*sc, s3 = d3*sc, s4 = d4*sc;
        float m = fmaxf(fmaxf(fmaxf(s0,s1), fmaxf(s2,s3)), s4);
        float e0 = __expf(s0-m), e1 = __expf(s1-m), e2 = __expf(s2-m),
              e3 = __expf(s3-m), e4 = __expf(s4-m);
        float inv = 1.f / (e0+e1+e2+e3+e4);
        float* wp = w + (size_t)gw * LL;
        wp[0]=e0*inv; wp[1]=e1*inv; wp[2]=e2*inv; wp[3]=e3*inv; wp[4]=e4*inv;
    }
}

// ---------------- scrambled-reshape gather ---------------------------------------
__global__ void k_gather(const float* __restrict__ y, const float* __restrict__ w,
                         float* __restrict__ out) {
    int ns = blockIdx.x;           // n*128 + s
    int n = ns >> 7;
    int s = ns & 127;
    float coef[LL];
    int   rowi[LL];
#pragma unroll
    for (int l = 0; l < LL; l++) {
        int f  = l * SS + s;
        int sp = f / 5;
        int lp = f - sp * 5;
        coef[l] = w[((size_t)n * SS + sp) * LL + lp];
        rowi[l] = sp + lp;
    }
    const float4* yb = (const float4*)y + (size_t)n * SC * 128;
    int c = threadIdx.x;   // 0..127 float4 lanes
    float4 acc = make_float4(0.f,0.f,0.f,0.f);
#pragma unroll
    for (int l = 0; l < LL; l++) {
        float4 v = yb[(size_t)rowi[l] * 128 + c];
        acc.x += coef[l]*v.x; acc.y += coef[l]*v.y;
        acc.z += coef[l]*v.z; acc.w += coef[l]*v.w;
    }
    ((float4*)out)[(size_t)ns * 128 + c] = acc;
}

// ---------------- attention 1 via tf32 MMA: per (n,h) block, S=128, dk=64 --------
// Writes output directly in [S,B,A,D] layout (fuses the x1->xa transpose).
#define Q_STR 68
#define V_STR 72
#define P_STR 132
__global__ void __launch_bounds__(256) attn1_tc(const float* __restrict__ q,
                                                const float* __restrict__ k,
                                                const float* __restrict__ v,
                                                float* __restrict__ o) {
    extern __shared__ unsigned sm[];
    unsigned* Qs = sm;
    unsigned* Ks = sm + 128 * Q_STR;
    unsigned* Ps = sm;                       // overlay (valid after QK phase)
    unsigned* Vs = sm + 2 * 128 * Q_STR;
    float* inv_l = (float*)(Vs + 128 * V_STR);

    int n = blockIdx.x >> 3, h = blockIdx.x & 7;
    int tid = threadIdx.x;
    int lane = tid & 31;
    int g = lane >> 2, tig = lane & 3;
    int m0 = (tid >> 5) * 16;                // warp -> 16 rows

    // load Q,K,V head tiles, convert to tf32
#pragma unroll
    for (int i = 0; i < 8; i++) {
        int idx = tid + 256 * i;             // 0..2047
        int s = idx >> 4, dq = idx & 15;
        size_t goff = ((size_t)(n * 128 + s)) * 512 + h * 64 + dq * 4;
        float4 vq = *(const float4*)(q + goff);
        float4 vk = *(const float4*)(k + goff);
        float4 vv = *(const float4*)(v + goff);
        *(uint4*)&Qs[s * Q_STR + dq * 4] =
            make_uint4(f2tf32(vq.x), f2tf32(vq.y), f2tf32(vq.z), f2tf32(vq.w));
        *(uint4*)&Ks[s * Q_STR + dq * 4] =
            make_uint4(f2tf32(vk.x), f2tf32(vk.y), f2tf32(vk.z), f2tf32(vk.w));
        *(uint4*)&Vs[s * V_STR + dq * 4] =
            make_uint4(f2tf32(vv.x), f2tf32(vv.y), f2tf32(vv.z), f2tf32(vv.w));
    }
    __syncthreads();

    // scores = Q @ K^T  (warp: 16 rows x 128 cols)
    float acc[16][4];
#pragma unroll
    for (int nt = 0; nt < 16; nt++)
#pragma unroll
        for (int i = 0; i < 4; i++) acc[nt][i] = 0.f;

#pragma unroll
    for (int kc = 0; kc < 8; kc++) {
        int kb = kc * 8;
        unsigned af[4];
        af[0] = Qs[(m0 + g) * Q_STR + kb + tig];
        af[1] = Qs[(m0 + 8 + g) * Q_STR + kb + tig];
        af[2] = Qs[(m0 + g) * Q_STR + kb + tig + 4];
        af[3] = Qs[(m0 + 8 + g) * Q_STR + kb + tig + 4];
#pragma unroll
        for (int nt = 0; nt < 16; nt++) {
            unsigned bf[2];
            bf[0] = Ks[(nt * 8 + g) * Q_STR + kb + tig];
            bf[1] = Ks[(nt * 8 + g) * Q_STR + kb + tig + 4];
            mma_tf32(acc[nt], af, bf);
        }
    }
    __syncthreads();   // Q,K dead everywhere -> safe to overlay Ps

    float* Pf = (float*)Ps;
#pragma unroll
    for (int nt = 0; nt < 16; nt++) {
        int col = nt * 8 + 2 * tig;
        Pf[(m0 + g) * P_STR + col]     = acc[nt][0];
        Pf[(m0 + g) * P_STR + col + 1] = acc[nt][1];
        Pf[(m0 + 8 + g) * P_STR + col]     = acc[nt][2];
        Pf[(m0 + 8 + g) * P_STR + col + 1] = acc[nt][3];
    }
    __syncthreads();

    // softmax: 2 threads per row, exp stored tf32-rounded (unnormalized)
    {
        int r = tid >> 1;
        int halfc = (tid & 1) * 64;
        float* row = Pf + r * P_STR + halfc;
        float mx = -1e30f;
#pragma unroll
        for (int j = 0; j < 64; j++) mx = fmaxf(mx, row[j]);
        mx = fmaxf(mx, __shfl_xor_sync(0xffffffffu, mx, 1));
        float mxs = mx * 0.125f;
        float sum = 0.f;
#pragma unroll
        for (int j = 0; j < 64; j++) {
            float e = __expf(row[j] * 0.125f - mxs);
            sum += e;
            ((unsigned*)row)[j] = f2tf32(e);
        }
        sum += __shfl_xor_sync(0xffffffffu, sum, 1);
        if ((tid & 1) == 0) inv_l[r] = 1.f / sum;
    }
    __syncthreads();

    // out = P @ V  (warp: 16 rows x 64 cols)
    float oacc[8][4];
#pragma unroll
    for (int nt = 0; nt < 8; nt++)
#pragma unroll
        for (int i = 0; i < 4; i++) oacc[nt][i] = 0.f;

#pragma unroll
    for (int kc = 0; kc < 16; kc++) {
        int kb = kc * 8;
        unsigned af[4];
        af[0] = Ps[(m0 + g) * P_STR + kb + tig];
        af[1] = Ps[(m0 + 8 + g) * P_STR + kb + tig];
        af[2] = Ps[(m0 + g) * P_STR + kb + tig + 4];
        af[3] = Ps[(m0 + 8 + g) * P_STR + kb + tig + 4];
#pragma unroll
        for (int nt = 0; nt < 8; nt++) {
            unsigned bf[2];
            bf[0] = Vs[(kb + tig) * V_STR + nt * 8 + g];
            bf[1] = Vs[(kb + tig + 4) * V_STR + nt * 8 + g];
            mma_tf32(oacc[nt], af, bf);
        }
    }

    float il0 = inv_l[m0 + g];
    float il1 = inv_l[m0 + 8 + g];
    // output in [S,B,A,D]: row(s) = s*256 + b*16 + a where n = a*16+b
    int a = n >> 4, b = n & 15;
    int s0 = m0 + g, s1 = m0 + 8 + g;
    size_t r0 = ((size_t)(s0 * 256 + b * 16 + a)) * 512 + h * 64;
    size_t r1 = ((size_t)(s1 * 256 + b * 16 + a)) * 512 + h * 64;
#pragma unroll
    for (int nt = 0; nt < 8; nt++) {
        int col = nt * 8 + 2 * tig;
        *(float2*)&o[r0 + col] =
            make_float2(oacc[nt][0] * il0, oacc[nt][1] * il0);
        *(float2*)&o[r1 + col] =
            make_float2(oacc[nt][2] * il1, oacc[nt][3] * il1);
    }
}

// ---------------- attention 2: per sb row (2048), seq=A=16, 8 heads ---------------
// Reads xa [S,B,A,D]; writes xf in [A,B,S,D] layout as tf32 (fuses transpose+cvt).
__global__ void k_attn2(const float* __restrict__ xa, unsigned* __restrict__ o) {
    __shared__ float hs[16*516];
    __shared__ float sc[16*16];
    __shared__ float ps[16*17];
    int sb = blockIdx.x;                      // s*16 + b
    int s_idx = sb >> 4, b_idx = sb & 15;
    const float4* src = (const float4*)(xa + (size_t)sb * 16 * DD);
    for (int it = threadIdx.x; it < 16*128; it += 256) {
        int r = it >> 7, c = it & 127;
        float4 vv = src[it];
        float* dst = hs + r*516 + c*4;
        dst[0]=vv.x; dst[1]=vv.y; dst[2]=vv.z; dst[3]=vv.w;
    }
    __syncthreads();
    int i = threadIdx.x >> 4;
    int j = threadIdx.x & 15;
    for (int h = 0; h < HH; h++) {
        int base = h * 64;
        const float* hi = hs + i*516 + base;
        const float* hj = hs + j*516 + base;
        float dot = 0.f;
#pragma unroll
        for (int d = 0; d < 64; d++) dot += hi[d]*hj[d];
        sc[i*16 + j] = dot * 0.125f;
        __syncthreads();
        if (threadIdx.x < 16) {
            int r = threadIdx.x;
            float m = -1e30f;
            for (int jj = 0; jj < 16; jj++) m = fmaxf(m, sc[r*16+jj]);
            float sum = 0.f;
            for (int jj = 0; jj < 16; jj++) {
                float e = __expf(sc[r*16+jj] - m);
                ps[r*17+jj] = e;
                sum += e;
            }
            float inv = 1.f / sum;
            for (int jj = 0; jj < 16; jj++) ps[r*17+jj] *= inv;
        }
        __syncthreads();
        for (int e = threadIdx.x; e < 16*64; e += 256) {
            int r = e >> 6, d = e & 63;     // r = a index
            float acc = 0.f;
#pragma unroll
            for (int jj = 0; jj < 16; jj++) acc += ps[r*17+jj] * hs[jj*516 + base + d];
            // dst row in [A,B,S,D]: (a*16+b)*128 + s
            o[((size_t)((r*16 + b_idx)*128 + s_idx)) * DD + base + d] = f2tf32(acc);
        }
        __syncthreads();
    }
}

// =================================================================================
extern "C" void kernel_launch(void* const* d_in, const int* in_sizes, int n_in,
                              void* d_out, int out_size) {
    const float* query = (const float*)d_in[0];
    const float* key   = (const float*)d_in[1];
    const float* value = (const float*)d_in[2];
    // d_in[3] = mask (unused by reference)
    const float* padq  = (const float*)d_in[4];
    const float* padk  = (const float*)d_in[5];
    const float* Wq    = (const float*)d_in[6];
    const float* bq    = (const float*)d_in[7];
    const float* Wk    = (const float*)d_in[8];
    const float* bk    = (const float*)d_in[9];
    const float* Wv    = (const float*)d_in[10];
    const float* bv    = (const float*)d_in[11];
    const float* Wo    = (const float*)d_in[12];
    const float* bo    = (const float*)d_in[13];
    float* out = (float*)d_out;

    unsigned *xcq, *xck, *vtf, *xf, *Wt;
    float *yq, *yk, *wq, *wk, *q, *k, *v, *xa;
    cudaGetSymbolAddress((void**)&xcq, g_xcq);
    cudaGetSymbolAddress((void**)&xck, g_xck);
    cudaGetSymbolAddress((void**)&yq,  g_yq);
    cudaGetSymbolAddress((void**)&yk,  g_yk);
    cudaGetSymbolAddress((void**)&wq,  g_wq);
    cudaGetSymbolAddress((void**)&wk,  g_wk);
    cudaGetSymbolAddress((void**)&q,   g_q);
    cudaGetSymbolAddress((void**)&k,   g_k);
    cudaGetSymbolAddress((void**)&v,   g_v);
    cudaGetSymbolAddress((void**)&vtf, g_vtf);
    cudaGetSymbolAddress((void**)&xa,  g_xa);
    cudaGetSymbolAddress((void**)&xf,  g_xf);
    cudaGetSymbolAddress((void**)&Wt,  g_Wt);

    const size_t WSZ = (size_t)DD * DD;

    // --- input conversions ---
    const int conc_blocks = (NN*SC*128) / 256;   // 16896
    k_concat_cvt<<<conc_blocks, 256>>>(query, padq, xcq);
    k_concat_cvt<<<conc_blocks, 256>>>(key,   padk, xck);
    k_cvt<<<(int)(WSZ/4 + 255)/256, 256>>>(Wq, Wt + 0*WSZ, (int)(WSZ/4));
    k_cvt<<<(int)(WSZ/4 + 255)/256, 256>>>(Wk, Wt + 1*WSZ, (int)(WSZ/4));
    k_cvt<<<(int)(WSZ/4 + 255)/256, 256>>>(Wv, Wt + 2*WSZ, (int)(WSZ/4));
    k_cvt<<<(int)(WSZ/4 + 255)/256, 256>>>(Wo, Wt + 3*WSZ, (int)(WSZ/4));
    k_cvt<<<(NN*SS*DD/4 + 255)/256, 256>>>(value, vtf, NN*SS*DD/4);

    // --- projections (tensor-core, cp.async 3-stage pipelined) ---
    const int gemm_smem = NSTG * 2 * STG_WORDS * 4;   // 110592 B
    cudaFuncSetAttribute(gemm_tc3, cudaFuncAttributeMaxDynamicSharedMemorySize, gemm_smem);
    dim3 gproj(DD/128, (NN*SC)/128);             // (4, 264)
    gemm_tc3<<<gproj, 256, gemm_smem>>>(xcq, Wt + 0*WSZ, bq, yq);
    gemm_tc3<<<gproj, 256, gemm_smem>>>(xck, Wt + 1*WSZ, bk, yk);
    dim3 gv(DD/128, (NN*SS)/128);                // (4, 256)
    gemm_tc3<<<gv, 256, gemm_smem>>>(vtf, Wt + 2*WSZ, bv, v);

    // --- local window reweighting ---
    k_weights<<<(NN*SS)/4, 128>>>(yq, wq);
    k_weights<<<(NN*SS)/4, 128>>>(yk, wk);
    k_gather<<<NN*SS, 128>>>(yq, wq, q);
    k_gather<<<NN*SS, 128>>>(yk, wk, k);

    // --- attention 1 (writes [S,B,A,D]) ---
    const int attn1_smem = 26752 * 4;            // 107008 B
    cudaFuncSetAttribute(attn1_tc, cudaFuncAttributeMaxDynamicSharedMemorySize, attn1_smem);
    attn1_tc<<<NN*HH, 256, attn1_smem>>>(q, k, v, xa);

    // --- attention 2 (reads [S,B,A,D], writes tf32 [A,B,S,D]) ---
    k_attn2<<<SS*BB, 256>>>(xa, xf);

    // --- output projection ---
    gemm_tc3<<<gv, 256, gemm_smem>>>(xf, Wt + 3*WSZ, bo, out);
}